// round 17
// baseline (speedup 1.0000x reference)
#include <cuda_runtime.h>
#include <cuda_bf16.h>
#include <cuda_fp16.h>
#include <cstdint>

// Problem constants
#define Bq   4
#define Nq   8192
#define DIMq 512
#define HEADSq 8
#define DHq  64
#define INNERq 512
#define QV_COLS 1024               // q | v (k never materialized)
#define M_TOTAL (Bq * Nq)          // 32768
#define BH (Bq * HEADSq)           // 32
#define SCALEq 0.125f
#define CHUNKS 32
#define REC 65

// ---------------- scratch (device globals; no allocation allowed) ----------
__device__ __align__(128) __half g_qkv[M_TOTAL * QV_COLS];      // 67 MB fp16
__device__ __align__(128) __half g_xh[M_TOTAL * DIMq];
__device__ __align__(128) __half g_Rh[M_TOTAL * INNERq];
__device__ __align__(128) __half g_Wqh[QV_COLS * DIMq];         // [Wq; Wv]
__device__ __align__(128) __half g_Woh[DIMq * INNERq];
__device__ __align__(128) __half g_u[BH * 8 * DIMq];            // u[bh][cb][512]
__device__ float g_gq[BH * DHq];
__device__ float g_gk[BH * DHq];
__device__ float g_part[BH * CHUNKS * REC];
__device__ float g_ypart[(size_t)BH * CHUNKS * 8 * DIMq];       // 16.8 MB
__device__ float g_wsum[BH * CHUNKS];

// =================== base-ISA helpers (sm_80+: cp.async / ldmatrix / mma) ===
__device__ __forceinline__ uint32_t smem_u32(const void* p) {
    uint32_t a;
    asm("{ .reg .u64 t; cvta.to.shared.u64 t, %1; cvt.u32.u64 %0, t; }"
        : "=r"(a) : "l"(p));
    return a;
}
__device__ __forceinline__ void cp_async16(uint32_t dst, const void* src) {
    asm volatile("cp.async.cg.shared.global [%0], [%1], 16;"
                 :: "r"(dst), "l"(src));
}
__device__ __forceinline__ void cp_commit() {
    asm volatile("cp.async.commit_group;");
}
template <int N>
__device__ __forceinline__ void cp_wait() {
    asm volatile("cp.async.wait_group %0;" :: "n"(N));
}
__device__ __forceinline__ void ldsm_x4(uint32_t addr, uint32_t* r) {
    asm volatile("ldmatrix.sync.aligned.m8n8.x4.shared.b16 {%0,%1,%2,%3}, [%4];"
                 : "=r"(r[0]), "=r"(r[1]), "=r"(r[2]), "=r"(r[3]) : "r"(addr));
}
__device__ __forceinline__ void mma_16816(float* c, const uint32_t* a,
                                          uint32_t b0, uint32_t b1) {
    asm volatile(
        "mma.sync.aligned.m16n8k16.row.col.f32.f16.f16.f32 "
        "{%0,%1,%2,%3}, {%4,%5,%6,%7}, {%8,%9}, {%0,%1,%2,%3};"
        : "+f"(c[0]), "+f"(c[1]), "+f"(c[2]), "+f"(c[3])
        : "r"(a[0]), "r"(a[1]), "r"(a[2]), "r"(a[3]), "r"(b0), "r"(b1));
}

// =================== converts ================================================
__global__ __launch_bounds__(256)
void convert_h_kernel(const float* __restrict__ in, __half* __restrict__ hi) {
    size_t i = ((size_t)blockIdx.x * 256 + threadIdx.x) * 4;
    float4 v = *reinterpret_cast<const float4*>(in + i);
    __half2 h0 = __float22half2_rn(make_float2(v.x, v.y));
    __half2 h1 = __float22half2_rn(make_float2(v.z, v.w));
    *reinterpret_cast<uint2*>(hi + i) = make_uint2(
        *reinterpret_cast<uint32_t*>(&h0), *reinterpret_cast<uint32_t*>(&h1));
}

// W_qkv rows {0-511 (q), 1024-1535 (v)} -> Wqh[1024x512] fp16
__global__ __launch_bounds__(256)
void convert_wqv_kernel(const float* __restrict__ W, __half* __restrict__ out) {
    size_t i = ((size_t)blockIdx.x * 256 + threadIdx.x) * 4;
    int row = (int)(i >> 9);
    int src_row = row < 512 ? row : row + 512;
    size_t si = (size_t)src_row * 512 + (i & 511);
    float4 v = *reinterpret_cast<const float4*>(W + si);
    __half2 h0 = __float22half2_rn(make_float2(v.x, v.y));
    __half2 h1 = __float22half2_rn(make_float2(v.z, v.w));
    *reinterpret_cast<uint2*>(out + i) = make_uint2(
        *reinterpret_cast<uint32_t*>(&h0), *reinterpret_cast<uint32_t*>(&h1));
}

// =================== HMMA fp16 x1 GEMM (BK=64, XOR swizzle, 1 sync/kblock) ==
#define AB_TILE_B 16384
#define NSTAGE   3
#define STAGE_TOT (2 * AB_TILE_B)
#define GSMEM_BYTES (NSTAGE * STAGE_TOT)   // 98304 B

template <bool BIAS, typename OT>
__global__ __launch_bounds__(128, 2)
void gemm_mma_x1(const __half* __restrict__ Ah, const __half* __restrict__ Bh,
                 const float* __restrict__ bias, OT* __restrict__ C, int Ntot) {
    extern __shared__ __align__(128) char smem[];
    const uint32_t sb = smem_u32(smem);
    const int tid = threadIdx.x;
    const int wid = tid >> 5, lane = tid & 31;
    const int wm = wid & 1;
    const int wn = wid >> 1;
    const int bm = blockIdx.y * 128;
    const int bn = blockIdx.x * 128;

    const __half* srcA = Ah + (size_t)bm * 512;
    const __half* srcB = Bh + (size_t)bn * 512;

#define ISSUE_STAGE(BUF, K0)                                                   \
    {                                                                          \
        uint32_t baseA = sb + (BUF) * STAGE_TOT;                               \
        uint32_t baseB = baseA + AB_TILE_B;                                    \
        _Pragma("unroll")                                                      \
        for (int i = 0; i < 8; i++) {                                          \
            int ch = i * 128 + tid;                                            \
            int r = ch >> 3, c = ch & 7;                                       \
            uint32_t pc = (uint32_t)(c ^ (r & 7)) << 4;                        \
            cp_async16(baseA + r * 128 + pc,                                   \
                       srcA + (size_t)r * 512 + (K0) + c * 8);                 \
            cp_async16(baseB + r * 128 + pc,                                   \
                       srcB + (size_t)r * 512 + (K0) + c * 8);                 \
        }                                                                      \
        cp_commit();                                                           \
    }

    float acc[4][8][4];
#pragma unroll
    for (int i = 0; i < 4; i++)
#pragma unroll
        for (int j = 0; j < 8; j++)
#pragma unroll
            for (int k = 0; k < 4; k++) acc[i][j][k] = 0.f;

    ISSUE_STAGE(0, 0)
    ISSUE_STAGE(1, 64)

    const uint32_t a_row = (lane & 15);
    const int a_cbase = (lane >> 4);
    const uint32_t b_row = (lane & 7) + ((lane >> 4) & 1) * 8;
    const int b_cbase = ((lane >> 3) & 1);

#pragma unroll 1
    for (int kb = 0; kb < 8; kb++) {
        if (kb < 7) cp_wait<1>(); else cp_wait<0>();
        __syncthreads();
        if (kb < 6) ISSUE_STAGE((kb + 2) % NSTAGE, (kb + 2) * 64);

        const uint32_t sA = sb + (kb % NSTAGE) * STAGE_TOT;
        const uint32_t sB = sA + AB_TILE_B;
#pragma unroll
        for (int ks = 0; ks < 4; ks++) {
            const int ca = ks * 2 + a_cbase;
            const int cb = ks * 2 + b_cbase;
            uint32_t aH[4][4], bH[4][4];
#pragma unroll
            for (int mt = 0; mt < 4; mt++) {
                uint32_t r = wm * 64 + mt * 16 + a_row;
                ldsm_x4(sA + r * 128 + ((uint32_t)(ca ^ (r & 7)) << 4), aH[mt]);
            }
#pragma unroll
            for (int nt2 = 0; nt2 < 4; nt2++) {
                uint32_t r = wn * 64 + nt2 * 16 + b_row;
                ldsm_x4(sB + r * 128 + ((uint32_t)(cb ^ (r & 7)) << 4), bH[nt2]);
            }
#pragma unroll
            for (int mt = 0; mt < 4; mt++)
#pragma unroll
                for (int nt2 = 0; nt2 < 4; nt2++) {
                    mma_16816(acc[mt][nt2 * 2 + 0], aH[mt], bH[nt2][0], bH[nt2][1]);
                    mma_16816(acc[mt][nt2 * 2 + 1], aH[mt], bH[nt2][2], bH[nt2][3]);
                }
        }
    }
#undef ISSUE_STAGE

#pragma unroll
    for (int mt = 0; mt < 4; mt++) {
        int row = bm + wm * 64 + mt * 16 + (lane >> 2);
#pragma unroll
        for (int nt = 0; nt < 8; nt++) {
            int col = bn + wn * 64 + nt * 8 + 2 * (lane & 3);
            float bx = 0.f, by = 0.f;
            if (BIAS) { bx = __ldg(bias + col); by = __ldg(bias + col + 1); }
            float v00 = acc[mt][nt][0] + bx, v01 = acc[mt][nt][1] + by;
            float v10 = acc[mt][nt][2] + bx, v11 = acc[mt][nt][3] + by;
            if constexpr (sizeof(OT) == 2) {
                *reinterpret_cast<__half2*>((__half*)C + (size_t)row * Ntot + col) =
                    __floats2half2_rn(v00, v01);
                *reinterpret_cast<__half2*>((__half*)C + (size_t)(row + 8) * Ntot + col) =
                    __floats2half2_rn(v10, v11);
            } else {
                *reinterpret_cast<float2*>((float*)C + (size_t)row * Ntot + col) =
                    make_float2(v00, v01);
                *reinterpret_cast<float2*>((float*)C + (size_t)(row + 8) * Ntot + col) =
                    make_float2(v10, v11);
            }
        }
    }
}

// ============ fused q softmax partial (reads q slab of qkv) =================
#define FPAD 72

__global__ __launch_bounds__(256)
void fused_softmax_partial(const __half* __restrict__ qkv,
                           const float* __restrict__ wq,
                           const unsigned char* __restrict__ mask,
                           float* __restrict__ part) {
    __shared__ __align__(16) __half sq[256 * FPAD];
    __shared__ float swv[64];
    __shared__ float sw[256];
    __shared__ float red[256];
    __shared__ float sv[4][64];

    const int chunk = blockIdx.x, bh = blockIdx.y;
    const int b = bh >> 3, h = bh & 7;
    const int tid = threadIdx.x;
    const int row0 = b * Nq + h * 1024 + chunk * 32;

#pragma unroll
    for (int i = 0; i < 8; i++) {
        int ch = i * 256 + tid;
        int tl = ch >> 3, d8 = ch & 7;
        const __half* src = qkv + (size_t)(row0 + (tl >> 3)) * QV_COLS
                            + (tl & 7) * 64 + d8 * 8;
        *reinterpret_cast<uint4*>(sq + tl * FPAD + d8 * 8) =
            *reinterpret_cast<const uint4*>(src);
    }
    if (tid < 64) swv[tid] = wq[tid];
    __syncthreads();

    float dot = 0.f;
    const __half* q = sq + tid * FPAD;
#pragma unroll
    for (int d = 0; d < 64; d += 2) {
        float2 qq = __half22float2(*reinterpret_cast<const __half2*>(q + d));
        dot += qq.x * swv[d] + qq.y * swv[d + 1];
    }
    float w = __expf(dot * SCALEq);
    if (mask[b * Nq + chunk * 256 + tid]) w = 0.f;
    sw[tid] = w;
    red[tid] = w;
    __syncthreads();
    for (int s = 128; s > 0; s >>= 1) {
        if (tid < s) red[tid] += red[tid + s];
        __syncthreads();
    }

    const int d = tid & 63, g = tid >> 6;
    float acc = 0.f;
#pragma unroll 8
    for (int tl = g * 64; tl < g * 64 + 64; tl++)
        acc += sw[tl] * __half2float(sq[tl * FPAD + d]);
    sv[g][d] = acc;
    __syncthreads();
    if (tid < 64) {
        float* rec = part + (size_t)(bh * CHUNKS + chunk) * REC;
        rec[tid] = sv[0][tid] + sv[1][tid] + sv[2][tid] + sv[3][tid];
        if (tid == 0) rec[64] = red[0];
    }
}

__global__ void finalize_reduce(const float* __restrict__ part,
                                float* __restrict__ gout) {
    int bh = blockIdx.x;
    int d = threadIdx.x;
    const float* base = part + (size_t)bh * CHUNKS * REC;
    float v = 0.f, w = 0.f;
#pragma unroll
    for (int c = 0; c < CHUNKS; c++) {
        v += base[c * REC + d];
        w += base[c * REC + 64];
    }
    gout[bh * 64 + d] = v / w;
}

// =================== k path WITHOUT materializing k =========================
// u[bh,cb][c] = sum_d (w_k[d]*gq[bh][d]) * W_qkv[512+cb*64+d][c]  (fp16 out)
__global__ __launch_bounds__(256)
void make_u(const float* __restrict__ W_qkv, const float* __restrict__ w_k,
            const float* __restrict__ gq, __half* __restrict__ u) {
    int bh = blockIdx.x >> 3, cb = blockIdx.x & 7;
    int t = threadIdx.x;
    __shared__ float coeff[64];
    if (t < 64) coeff[t] = w_k[t] * gq[bh * 64 + t];
    __syncthreads();
    const float* Wb = W_qkv + (size_t)(512 + cb * 64) * 512;
    float a0 = 0.f, a1 = 0.f;
#pragma unroll 8
    for (int d = 0; d < 64; d++) {
        float cd = coeff[d];
        a0 += cd * Wb[(size_t)d * 512 + t];
        a1 += cd * Wb[(size_t)d * 512 + t + 256];
    }
    u[(size_t)blockIdx.x * 512 + t] = __float2half_rn(a0);
    u[(size_t)blockIdx.x * 512 + t + 256] = __float2half_rn(a1);
}

// One pass over xh: logits + exp + per-cb weighted x sums. grid (CHUNKS, BH).
#define XPAD 520   // halfs per x row in smem (1040 B, 16B multiple)

__global__ __launch_bounds__(256)
void fused_k_partial(const __half* __restrict__ xh, const __half* __restrict__ u,
                     const unsigned char* __restrict__ mask,
                     float* __restrict__ ypart, float* __restrict__ wsum) {
    __shared__ __align__(16) __half sx[32 * XPAD];   // 33280 B
    __shared__ __align__(16) __half su[8 * 512];     //  8192 B
    __shared__ float sw[256];
    __shared__ float red[256];

    const int chunk = blockIdx.x, bh = blockIdx.y;
    const int b = bh >> 3, h = bh & 7;
    const int tid = threadIdx.x;
    const int row0 = b * Nq + h * 1024 + chunk * 32;

    // stage 32 x-rows (512 halfs each): 2048 8-half chunks, 8 per thread
#pragma unroll
    for (int i = 0; i < 8; i++) {
        int ch = i * 256 + tid;
        int r = ch >> 6, c8 = ch & 63;
        *reinterpret_cast<uint4*>(sx + r * XPAD + c8 * 8) =
            *reinterpret_cast<const uint4*>(xh + (size_t)(row0 + r) * 512 + c8 * 8);
    }
    // stage u[bh]: 8x512 halfs = 512 chunks, 2 per thread
#pragma unroll
    for (int i = 0; i < 2; i++) {
        int ch = i * 256 + tid;
        *reinterpret_cast<uint4*>(su + ch * 8) =
            *reinterpret_cast<const uint4*>(u + (size_t)bh * 4096 + ch * 8);
    }
    __syncthreads();

    // token tid: rl = tid>>3, cb = tid&7; logit = SCALE * x_rl . u_cb
    const int rl = tid >> 3, cbt = tid & 7;
    float dot = 0.f;
    const __half* xr = sx + rl * XPAD;
    const __half* ur = su + cbt * 512;
#pragma unroll 16
    for (int d = 0; d < 512; d += 2) {
        float2 xv = __half22float2(*reinterpret_cast<const __half2*>(xr + d));
        float2 uv = __half22float2(*reinterpret_cast<const __half2*>(ur + d));
        dot += xv.x * uv.x + xv.y * uv.y;
    }
    float w = __expf(dot * SCALEq);
    if (mask[b * Nq + chunk * 256 + tid]) w = 0.f;
    sw[tid] = w;
    red[tid] = w;
    __syncthreads();
    for (int s = 128; s > 0; s >>= 1) {
        if (tid < s) red[tid] += red[tid + s];
        __syncthreads();
    }
    if (tid == 0) wsum[bh * CHUNKS + chunk] = red[0];

    // y[cb][c] = sum_rl sw[rl*8+cb] * x[rl][c]; thread handles c=2*tid, 2 cols
    const int c0 = tid * 2;
    float acc[8][2];
#pragma unroll
    for (int cb = 0; cb < 8; cb++) { acc[cb][0] = 0.f; acc[cb][1] = 0.f; }
#pragma unroll 4
    for (int r = 0; r < 32; r++) {
        float2 xv = __half22float2(*reinterpret_cast<const __half2*>(
            sx + r * XPAD + c0));
        const float* swr = sw + r * 8;
#pragma unroll
        for (int cb = 0; cb < 8; cb++) {
            acc[cb][0] += swr[cb] * xv.x;
            acc[cb][1] += swr[cb] * xv.y;
        }
    }
    float* out = ypart + (size_t)(bh * CHUNKS + chunk) * 4096;
#pragma unroll
    for (int cb = 0; cb < 8; cb++)
        *reinterpret_cast<float2*>(out + cb * 512 + c0) =
            make_float2(acc[cb][0], acc[cb][1]);
}

// gk[bh][d] = (sum_cb sum_c ysum[cb][c] * W_qkv[512+cb*64+d][c]) / S
__global__ __launch_bounds__(256)
void finalize_gk(const float* __restrict__ ypart, const float* __restrict__ wsum,
                 const float* __restrict__ W_qkv, float* __restrict__ gk) {
    __shared__ float ysum[8 * 512];
    __shared__ float ss[32];
    __shared__ float pr[256];
    int bh = blockIdx.x;
    int t = threadIdx.x;

#pragma unroll
    for (int i = 0; i < 16; i++) {
        int idx = i * 256 + t;
        float s = 0.f;
        const float* base = ypart + (size_t)bh * CHUNKS * 4096 + idx;
#pragma unroll 8
        for (int ch = 0; ch < CHUNKS; ch++) s += base[(size_t)ch * 4096];
        ysum[idx] = s;
    }
    if (t < 32) ss[t] = wsum[bh * CHUNKS + t];
    __syncthreads();
    float S = 0.f;
#pragma unroll
    for (int i = 0; i < 32; i++) S += ss[i];

    int d = t & 63, grp = t >> 6;
    float acc = 0.f;
#pragma unroll
    for (int j = 0; j < 2; j++) {
        int cb = grp * 2 + j;
        const float* wrow = W_qkv + (size_t)(512 + cb * 64 + d) * 512;
        const float* yrow = ysum + cb * 512;
#pragma unroll 4
        for (int c = 0; c < 512; c += 4) {
            float4 w4 = *reinterpret_cast<const float4*>(wrow + c);
            acc += yrow[c] * w4.x + yrow[c + 1] * w4.y
                 + yrow[c + 2] * w4.z + yrow[c + 3] * w4.w;
        }
    }
    pr[t] = acc;
    __syncthreads();
    if (t < 64)
        gk[bh * 64 + t] = (pr[t] + pr[t + 64] + pr[t + 128] + pr[t + 192]) / S;
}

// ============ compute_r via HMMA: R = A'[256x64] @ Mw^T + q + b_r ===========
#define CR_ROWS 32
#define CR_PAD  72

__global__ __launch_bounds__(256)
void compute_r_mma(const __half* __restrict__ qkv,
                   const float* __restrict__ gk,
                   const float* __restrict__ W_r,
                   const float* __restrict__ b_r,
                   __half* __restrict__ Rh) {
    __shared__ __align__(16) __half sA[256 * CR_PAD];
    __shared__ __align__(16) __half sB[64 * CR_PAD];
    __shared__ float sbr[64];

    const int tid = threadIdx.x;
    const int wid = tid >> 5, lane = tid & 31;
    const int row0 = blockIdx.x * CR_ROWS;
    const int bh = (row0 >> 13) * 8 + ((row0 & (Nq - 1)) >> 10);

#pragma unroll
    for (int i = 0; i < 8; i++) {
        int ch = i * 256 + tid;
        int tok = ch >> 3, d8 = ch & 7;
        const __half* src = qkv + (size_t)(row0 + (tok >> 3)) * QV_COLS
                            + 512 + (tok & 7) * 64 + d8 * 8;
        *reinterpret_cast<uint4*>(sA + tok * CR_PAD + d8 * 8) =
            *reinterpret_cast<const uint4*>(src);
    }

    {
        int e = tid >> 2, db = (tid & 3) * 16;
        const float* wr = W_r + e * 64 + db;
        const float* gkp = gk + bh * 64 + db;
        __half tmp[16];
#pragma unroll
        for (int j = 0; j < 16; j += 4) {
            float4 w4 = *reinterpret_cast<const float4*>(wr + j);
            float4 g4 = *reinterpret_cast<const float4*>(gkp + j);
            tmp[j + 0] = __float2half_rn(w4.x * g4.x);
            tmp[j + 1] = __float2half_rn(w4.y * g4.y);
            tmp[j + 2] = __float2half_rn(w4.z * g4.z);
            tmp[j + 3] = __float2half_rn(w4.w * g4.w);
        }
        *reinterpret_cast<uint4*>(sB + e * CR_PAD + db) =
            *reinterpret_cast<uint4*>(tmp);
        *reinterpret_cast<uint4*>(sB + e * CR_PAD + db + 8) =
            *reinterpret_cast<uint4*>(tmp + 8);
    }
    if (tid < 64) sbr[tid] = b_r[tid];
    __syncthreads();

    const uint32_t sAu = smem_u32(sA);
    const uint32_t sBu = smem_u32(sB);
    const uint32_t a_row = (lane & 15);
    const uint32_t a_half = (lane >> 4) * 16;
    const uint32_t b_row = (lane & 7) + ((lane >> 4) & 1) * 8;
    const uint32_t b_half = ((lane >> 3) & 1) * 16;

    float c[2][8][4];
#pragma unroll
    for (int i = 0; i < 2; i++)
#pragma unroll
        for (int j = 0; j < 8; j++)
#pragma unroll
            for (int k = 0; k < 4; k++) c[i][j][k] = 0.f;

#pragma unroll
    for (int k = 0; k < 4; k++) {
        uint32_t aH[2][4], bH[4][4];
#pragma unroll
        for (int mt = 0; mt < 2; mt++)
            ldsm_x4(sAu + (wid * 32 + mt * 16 + a_row) * 144 + a_half + k * 32,
                    aH[mt]);
#pragma unroll
        for (int nt2 = 0; nt2 < 4; nt2++)
            ldsm_x4(sBu + (nt2 * 16 + b_row) * 144 + b_half + k * 32, bH[nt2]);
#pragma unroll
        for (int mt = 0; mt < 2; mt++)
#pragma unroll
            for (int nt2 = 0; nt2 < 4; nt2++) {
                mma_16816(c[mt][nt2 * 2 + 0], aH[mt], bH[nt2][0], bH[nt2][1]);
                mma_16816(c[mt][nt2 * 2 + 1], aH[mt], bH[nt2][2], bH[nt2][3]);
            }
    }

#pragma unroll
    for (int mt = 0; mt < 2; mt++) {
        int t0 = wid * 32 + mt * 16 + (lane >> 2);
#pragma unroll
        for (int nt = 0; nt < 8; nt++) {
            int e = nt * 8 + 2 * (lane & 3);
            float br0 = sbr[e], br1 = sbr[e + 1];
#pragma unroll
            for (int half = 0; half < 2; half++) {
                int t = t0 + half * 8;
                size_t base = (size_t)(row0 + (t >> 3));
                int col = (t & 7) * 64 + e;
                float2 q = __half22float2(*reinterpret_cast<const __half2*>(
                    qkv + base * QV_COLS + col));
                float o0 = c[mt][nt][half * 2 + 0] + q.x + br0;
                float o1 = c[mt][nt][half * 2 + 1] + q.y + br1;
                __half2 hv = __floats2half2_rn(o0, o1);
                *reinterpret_cast<__half2*>(Rh + base * INNERq + col) = hv;
            }
        }
    }
}

// ---------------- launcher --------------------------------------------------
extern "C" void kernel_launch(void* const* d_in, const int* in_sizes, int n_in,
                              void* d_out, int out_size) {
    const float* x     = (const float*)d_in[0];
    const unsigned char* mask = (const unsigned char*)d_in[1];
    const float* W_qkv = (const float*)d_in[2];
    const float* w_q   = (const float*)d_in[3];
    const float* w_k   = (const float*)d_in[4];
    const float* W_r   = (const float*)d_in[5];
    const float* b_r   = (const float*)d_in[6];
    const float* W_out = (const float*)d_in[7];
    const float* b_out = (const float*)d_in[8];
    float* out = (float*)d_out;

    float *gq, *gk, *part, *ypart, *wsum;
    __half *qkv, *xh, *Rh, *Wqh, *Woh, *u;
    cudaGetSymbolAddress((void**)&qkv,   g_qkv);
    cudaGetSymbolAddress((void**)&gq,    g_gq);
    cudaGetSymbolAddress((void**)&gk,    g_gk);
    cudaGetSymbolAddress((void**)&part,  g_part);
    cudaGetSymbolAddress((void**)&ypart, g_ypart);
    cudaGetSymbolAddress((void**)&wsum,  g_wsum);
    cudaGetSymbolAddress((void**)&xh,    g_xh);
    cudaGetSymbolAddress((void**)&Rh,    g_Rh);
    cudaGetSymbolAddress((void**)&Wqh,   g_Wqh);
    cudaGetSymbolAddress((void**)&Woh,   g_Woh);
    cudaGetSymbolAddress((void**)&u,     g_u);

    static int smem_set = 0;
    if (!smem_set) {
        cudaFuncSetAttribute((const void*)gemm_mma_x1<false, __half>,
                             cudaFuncAttributeMaxDynamicSharedMemorySize, GSMEM_BYTES);
        cudaFuncSetAttribute((const void*)gemm_mma_x1<true, float>,
                             cudaFuncAttributeMaxDynamicSharedMemorySize, GSMEM_BYTES);
        smem_set = 1;
    }

    // 0) conversions: x -> fp16; [Wq;Wv] -> fp16; W_out -> fp16
    convert_h_kernel<<<(M_TOTAL * DIMq) / 1024, 256>>>(x, xh);
    convert_wqv_kernel<<<(QV_COLS * DIMq) / 1024, 256>>>(W_qkv, Wqh);
    convert_h_kernel<<<(DIMq * INNERq) / 1024, 256>>>(W_out, Woh);

    // 1) [q|v] = x @ [Wq;Wv]^T  (HMMA, 1024 cols)
    gemm_mma_x1<false, __half><<<dim3(QV_COLS / 128, M_TOTAL / 128), 128,
                                 GSMEM_BYTES>>>(xh, Wqh, nullptr, qkv, QV_COLS);

    // 2) q softmax -> global_q
    fused_softmax_partial<<<dim3(CHUNKS, BH), 256>>>(qkv, w_q, mask, part);
    finalize_reduce<<<BH, 64>>>(part, gq);

    // 3) k softmax -> global_k (k never materialized; single pass over xh)
    make_u<<<BH * 8, 256>>>(W_qkv, w_k, gq, u);
    fused_k_partial<<<dim3(CHUNKS, BH), 256>>>(xh, u, mask, ypart, wsum);
    finalize_gk<<<BH, 256>>>(ypart, wsum, W_qkv, gk);

    // 4) r = (v*gk) @ W_r^T + b_r + q  (HMMA, fp16 in/out)
    compute_r_mma<<<M_TOTAL / CR_ROWS, 256>>>(qkv, gk, W_r, b_r, Rh);

    // 5) out = r @ W_out^T + b_out  (HMMA, fp32 output)
    gemm_mma_x1<true, float><<<dim3(INNERq / 128, M_TOTAL / 128), 128,
                               GSMEM_BYTES>>>(Rh, Woh, b_out, out, INNERq);
}